// round 13
// baseline (speedup 1.0000x reference)
#include <cuda_runtime.h>
#include <cstdint>

// ---------------------------------------------------------------------------
// AllPassMORRCirculantConv2d  (B=8, Cin=32, H=W=64, K=3, S=1, P=1, Cout=64)
// out[p*8+k] = sum_q (scale[q]*D) * rcp(K2 - 2AR*cos(phase_{p,q,k}))
// phase_{p,q,k} = sum_j inten[q*8+j] * w[p][q][(k-j)&7]   (circular conv n=8)
//
// R12: single-wave occupancy push. k-dim processed in 2 halves of 4 so ph2
//      drops 16->8 regs; live set ~64 regs -> __launch_bounds__(256,4) fits
//      WITHOUT spilling -> 4 blocks/SM, 592 slots >= 512 grid = ONE wave,
//      8 warps/SMSP to cover MUFU/LDS latency. Weights via LDS.128.
// ---------------------------------------------------------------------------

#define AA 0.8578
#define RR 0.8985

static constexpr float G2f  = (float)(2.0 * AA * RR);                   // 2AR
static constexpr float K2f  = (float)(1.0 + (AA * RR) * (AA * RR));     // 1+(AR)^2
static constexpr float Df   = (float)((AA * AA + RR * RR) - 1.0
                                      - (AA * RR) * (AA * RR));         // K1-K2
static constexpr float GAINf = 1.6666666666666667f;                     // sqrt(100/36)

#define PH 66
#define PW 66
#define NPAD (8 * 32 * PH * PW)

// smem tile geometry: 16 channels x 3 rows x 65 pair-columns (per phase)
#define TCH   16
#define TROWW 65
#define TSZ   (TCH * 3 * TROWW)      // 3120 float2 = 24960 B
#define CH_STRIDE_B (3 * TROWW * 8)  // bytes per channel in tile

typedef unsigned long long ull;

// Pre-shifted packed image: g_sq2[i] = { s[i], s[i+1] }, s = padded x^2*gain
__device__ float2 g_sq2[NPAD];

// ---------------- packed f32x2 helpers -------------------------------------
__device__ __forceinline__ ull pack2(float lo, float hi) {
    ull r;
    asm("mov.b64 %0, {%1, %2};" : "=l"(r) : "f"(lo), "f"(hi));
    return r;
}
__device__ __forceinline__ void unpack2(ull v, float& lo, float& hi) {
    asm("mov.b64 {%0, %1}, %2;" : "=f"(lo), "=f"(hi) : "l"(v));
}
__device__ __forceinline__ ull fma2(ull a, ull b, ull c) {
    ull d;
    asm("fma.rn.f32x2 %0, %1, %2, %3;" : "=l"(d) : "l"(a), "l"(b), "l"(c));
    return d;
}

// ---------------- Kernel 1: pad + square + gain + shift-pack ---------------
__device__ __forceinline__ float pad_val(const float* __restrict__ x, int j) {
    int px = j % PW;
    int t  = j / PW;
    int py = t % PH;
    int bc = t / PH;
    if (px >= 1 && px <= 64 && py >= 1 && py <= 64) {
        float u = x[bc * 4096 + (py - 1) * 64 + (px - 1)];
        return u * u * GAINf;
    }
    return 0.0f;
}

__global__ void prep_kernel(const float* __restrict__ x) {
    int i = blockIdx.x * blockDim.x + threadIdx.x;
    if (i >= NPAD) return;
    float v0 = pad_val(x, i);
    float v1 = (i + 1 < NPAD) ? pad_val(x, i + 1) : 0.0f;
    g_sq2[i] = make_float2(v0, v1);
}

// ---------------- Kernel 2: main -------------------------------------------
// block = 256 threads = 8 p-warps x 32 pixel-pairs (one row). grid = 512.
// q structure: 2 halves (16 ch each) x 2 groups (9 q = 8 ch) fully unrolled.
// k structure: per q, two halves of 4 k's (keeps ph regs at 8).
__global__ __launch_bounds__(256, 4)
void morr_main_kernel(const float* __restrict__ weight,   // [8][36][8]
                      const float* __restrict__ mscale,   // [19]
                      float* __restrict__ out)            // [8][64][64][64]
{
    __shared__ float2 sp[TSZ];           // staged window pairs: 24960 B
    __shared__ ull    sww[8 * 36 * 8];   // {w,w} duplicated:    18432 B
    __shared__ float  ss2[36];           // scale[q] * D

    const int tid = threadIdx.x;
    const int b   = blockIdx.x >> 6;       // image
    const int y   = blockIdx.x & 63;       // row

    for (int i = tid; i < 2304; i += 256) {
        float wv = weight[i];
        sww[i] = pack2(wv, wv);
    }
    if (tid < 36) {
        float s = (tid < 18) ? mscale[tid] : -mscale[tid - 18];
        ss2[tid] = s * Df;
    }

    const int lane = tid & 31;
    const int p    = tid >> 5;             // warp index = output block p
    const int x    = lane * 2;             // even pixel of the pair

    const char*   spx  = reinterpret_cast<const char*>(sp) + x * 8;
    const float2* gsrc = g_sq2 + (b * 32) * (PH * PW) + y * PW;

    // acc[k] : pixel x ; acc[8+k] : pixel x+1   (channel p*8+k)
    float acc[16];
#pragma unroll
    for (int i = 0; i < 16; i++) acc[i] = 0.0f;

#pragma unroll 1
    for (int half = 0; half < 2; half++) {
        __syncthreads();                   // prior phase reads done
        const float2* g0 = gsrc + (half * TCH) * (PH * PW);
        for (int i = tid; i < TSZ; i += 256) {
            int c   = i / (3 * TROWW);
            int rem = i - c * (3 * TROWW);
            int rr  = rem / TROWW;
            int pc  = rem - rr * TROWW;
            sp[i] = g0[(c * PH + rr) * PW + pc];
        }
        __syncthreads();

#pragma unroll 1
        for (int grp = 0; grp < 2; grp++) {
            // channels (local) grp*8 .. grp*8+7 ; q = half*18 + grp*9 + ql
            const char* cbase = spx + grp * 8 * CH_STRIDE_B;
            const int   qbase = half * 18 + grp * 9;
            const ulonglong2* wq = reinterpret_cast<const ulonglong2*>(
                sww + p * 288 + qbase * 8);

#pragma unroll
            for (int ql = 0; ql < 9; ql++) {
                ull inten2[8];
#pragma unroll
                for (int t = 0; t < 8; t++) {
                    const int w  = ql * 8 + t;        // 0..71 within group
                    const int c  = w / 9;             // compile-time
                    const int r  = w % 9;
                    const int off = (c * 3 + r / 3) * TROWW * 8 + (r % 3) * 8;
                    inten2[t] = *reinterpret_cast<const ull*>(cbase + off);
                }

                ull w2[8];
#pragma unroll
                for (int m = 0; m < 4; m++) {
                    ulonglong2 wv = wq[ql * 4 + m];   // LDS.128
                    w2[2 * m]     = wv.x;
                    w2[2 * m + 1] = wv.y;
                }

                const float s2 = ss2[qbase + ql];

#pragma unroll
                for (int kh = 0; kh < 2; kh++) {
                    ull ph2[4] = {0ull, 0ull, 0ull, 0ull};
#pragma unroll
                    for (int j = 0; j < 8; j++) {
#pragma unroll
                        for (int kk = 0; kk < 4; kk++)
                            ph2[kk] = fma2(inten2[j],
                                           w2[(kh * 4 + kk - j) & 7],
                                           ph2[kk]);
                    }
#pragma unroll
                    for (int kk = 0; kk < 4; kk++) {
                        const int k = kh * 4 + kk;
                        float p0, p1;
                        unpack2(ph2[kk], p0, p1);
                        float c0 = __cosf(p0);
                        float c1 = __cosf(p1);
                        float d0 = fmaf(-G2f, c0, K2f);
                        float d1 = fmaf(-G2f, c1, K2f);
                        float r0, r1;
                        asm("rcp.approx.f32 %0, %1;" : "=f"(r0) : "f"(d0));
                        asm("rcp.approx.f32 %0, %1;" : "=f"(r1) : "f"(d1));
                        acc[k]     = fmaf(s2, r0, acc[k]);
                        acc[8 + k] = fmaf(s2, r1, acc[8 + k]);
                    }
                }
            }
        }
    }

    float* op = out + (b * 64 + p * 8) * 4096 + y * 64 + x;
#pragma unroll
    for (int k = 0; k < 8; k++)
        *reinterpret_cast<float2*>(op + k * 4096) = make_float2(acc[k], acc[8 + k]);
}

// ---------------- launch ----------------------------------------------------
extern "C" void kernel_launch(void* const* d_in, const int* in_sizes, int n_in,
                              void* d_out, int out_size)
{
    const float* x   = (const float*)d_in[0];   // (8,32,64,64)
    const float* wgt = (const float*)d_in[1];   // (8,36,8)
    const float* ms  = (const float*)d_in[2];   // (19,)
    float* out = (float*)d_out;                 // (8,64,64,64)

    prep_kernel<<<(NPAD + 255) / 256, 256>>>(x);
    morr_main_kernel<<<512, 256>>>(wgt, ms, out);
}

// round 14
// speedup vs baseline: 1.1635x; 1.1635x over previous
#include <cuda_runtime.h>
#include <cstdint>

// ---------------------------------------------------------------------------
// AllPassMORRCirculantConv2d  (B=8, Cin=32, H=W=64, K=3, S=1, P=1, Cout=64)
// out[p*8+k] = sum_q (scale[q]*D) * rcp(K2 - 2AR*cos(phase_{p,q,k}))
// phase_{p,q,k} = sum_j inten[q*8+j] * w[p][q][(k-j)&7]   (circular conv n=8)
//
// R13: revert to R11 structure (best), plus:
//      (a) prep kernel FUSED into main staging (no g_sq2 round-trip,
//          one launch instead of two),
//      (b) single-phase 32-channel tile (one stage + one sync),
//      (c) LDS.128 weight fetches.
//      Reg policy: __launch_bounds__(256,3) -- 64-reg caps spill (R10,R12).
// ---------------------------------------------------------------------------

#define AA 0.8578
#define RR 0.8985

static constexpr float G2f  = (float)(2.0 * AA * RR);                   // 2AR
static constexpr float K2f  = (float)(1.0 + (AA * RR) * (AA * RR));     // 1+(AR)^2
static constexpr float Df   = (float)((AA * AA + RR * RR) - 1.0
                                      - (AA * RR) * (AA * RR));         // K1-K2
static constexpr float GAINf = 1.6666666666666667f;                     // sqrt(100/36)

// smem tile geometry: 32 channels x 3 rows x 65 pair-columns
#define TROWW 65
#define TSZ   (32 * 3 * TROWW)       // 6240 float2 = 49920 B
#define CH_STRIDE_B (3 * TROWW * 8)  // bytes per channel in tile

typedef unsigned long long ull;

// ---------------- packed f32x2 helpers -------------------------------------
__device__ __forceinline__ ull pack2(float lo, float hi) {
    ull r;
    asm("mov.b64 %0, {%1, %2};" : "=l"(r) : "f"(lo), "f"(hi));
    return r;
}
__device__ __forceinline__ void unpack2(ull v, float& lo, float& hi) {
    asm("mov.b64 {%0, %1}, %2;" : "=f"(lo), "=f"(hi) : "l"(v));
}
__device__ __forceinline__ ull fma2(ull a, ull b, ull c) {
    ull d;
    asm("fma.rn.f32x2 %0, %1, %2, %3;" : "=l"(d) : "l"(a), "l"(b), "l"(c));
    return d;
}

// ---------------- main kernel ----------------------------------------------
// block = 256 threads = 8 p-warps x 32 pixel-pairs (one output row y of one
// image b). grid = 512 (b*64 + y).
// q structure: 4 groups x 9 q (one group = exactly 8 channels), fully
// unrolled -> all tap/weight offsets are compile-time immediates.
__global__ __launch_bounds__(256, 3)
void morr_main_kernel(const float* __restrict__ x,        // [8][32][64][64]
                      const float* __restrict__ weight,   // [8][36][8]
                      const float* __restrict__ mscale,   // [19]
                      float* __restrict__ out)            // [8][64][64][64]
{
    __shared__ float2 sp[TSZ];           // staged window pairs: 49920 B
    __shared__ ull    sww[8 * 36 * 8];   // {w,w} duplicated:    18432 B
    __shared__ float  ss2[36];           // scale[q] * D

    const int tid = threadIdx.x;
    const int b   = blockIdx.x >> 6;       // image
    const int y   = blockIdx.x & 63;       // output row

    for (int i = tid; i < 2304; i += 256) {
        float wv = weight[i];
        sww[i] = pack2(wv, wv);
    }
    if (tid < 36) {
        float s = (tid < 18) ? mscale[tid] : -mscale[tid - 18];
        ss2[tid] = s * Df;
    }

    // ---- fused staging: pad + square + gain + pair-pack, straight from x --
    // tile(c, rr, pc) = { s(c, y+rr, pc), s(c, y+rr, pc+1) } where s is the
    // padded squared image: s(c, pr, px) = x[c][pr-1][px-1]^2*GAIN if valid.
    {
        const float* xb = x + (b * 32) * 4096;
        for (int i = tid; i < TSZ; i += 256) {
            int c   = i / (3 * TROWW);
            int rem = i - c * (3 * TROWW);
            int rr  = rem / TROWW;
            int pc  = rem - rr * TROWW;
            int ir  = y + rr - 1;                    // input row
            float lo = 0.0f, hi = 0.0f;
            if (ir >= 0 && ir <= 63) {
                const float* xr = xb + c * 4096 + ir * 64;
                int icl = pc - 1;                    // input col for lo
                if (icl >= 0) {                      // icl <= 63 since pc<=64
                    float u = xr[icl];
                    lo = u * u * GAINf;
                }
                int ich = pc;                        // input col for hi
                if (ich <= 63) {
                    float u = xr[ich];
                    hi = u * u * GAINf;
                }
            }
            sp[i] = make_float2(lo, hi);
        }
    }
    __syncthreads();

    const int lane = tid & 31;
    const int p    = tid >> 5;             // warp index = output block p
    const int xp   = lane * 2;             // even pixel of the pair

    const char* spx = reinterpret_cast<const char*>(sp) + xp * 8;

    // acc[k] : pixel xp ; acc[8+k] : pixel xp+1   (channel p*8+k)
    float acc[16];
#pragma unroll
    for (int i = 0; i < 16; i++) acc[i] = 0.0f;

#pragma unroll 1
    for (int grp = 0; grp < 4; grp++) {
        // channels grp*8 .. grp*8+7  <->  q = grp*9 + ql
        const char* cbase = spx + grp * 8 * CH_STRIDE_B;
        const int   qbase = grp * 9;
        const ulonglong2* wq = reinterpret_cast<const ulonglong2*>(
            sww + p * 288 + qbase * 8);

#pragma unroll
        for (int ql = 0; ql < 9; ql++) {
            ull inten2[8];
#pragma unroll
            for (int t = 0; t < 8; t++) {
                const int w   = ql * 8 + t;          // 0..71 within group
                const int c   = w / 9;               // compile-time
                const int r   = w % 9;
                const int off = (c * 3 + r / 3) * TROWW * 8 + (r % 3) * 8;
                inten2[t] = *reinterpret_cast<const ull*>(cbase + off);
            }

            ull w2[8];
#pragma unroll
            for (int m = 0; m < 4; m++) {
                ulonglong2 wv = wq[ql * 4 + m];      // LDS.128
                w2[2 * m]     = wv.x;
                w2[2 * m + 1] = wv.y;
            }

            ull ph2[8] = {0ull, 0ull, 0ull, 0ull, 0ull, 0ull, 0ull, 0ull};
#pragma unroll
            for (int j = 0; j < 8; j++) {
#pragma unroll
                for (int k = 0; k < 8; k++)
                    ph2[k] = fma2(inten2[j], w2[(k - j) & 7], ph2[k]);
            }

            const float s2 = ss2[qbase + ql];
#pragma unroll
            for (int k = 0; k < 8; k++) {
                float p0, p1;
                unpack2(ph2[k], p0, p1);
                float c0 = __cosf(p0);
                float c1 = __cosf(p1);
                float d0 = fmaf(-G2f, c0, K2f);
                float d1 = fmaf(-G2f, c1, K2f);
                float r0, r1;
                asm("rcp.approx.f32 %0, %1;" : "=f"(r0) : "f"(d0));
                asm("rcp.approx.f32 %0, %1;" : "=f"(r1) : "f"(d1));
                acc[k]     = fmaf(s2, r0, acc[k]);
                acc[8 + k] = fmaf(s2, r1, acc[8 + k]);
            }
        }
    }

    float* op = out + (b * 64 + p * 8) * 4096 + y * 64 + xp;
#pragma unroll
    for (int k = 0; k < 8; k++)
        *reinterpret_cast<float2*>(op + k * 4096) = make_float2(acc[k], acc[8 + k]);
}

// ---------------- launch ----------------------------------------------------
extern "C" void kernel_launch(void* const* d_in, const int* in_sizes, int n_in,
                              void* d_out, int out_size)
{
    const float* x   = (const float*)d_in[0];   // (8,32,64,64)
    const float* wgt = (const float*)d_in[1];   // (8,36,8)
    const float* ms  = (const float*)d_in[2];   // (19,)
    float* out = (float*)d_out;                 // (8,64,64,64)

    morr_main_kernel<<<512, 256>>>(x, wgt, ms, out);
}

// round 16
// speedup vs baseline: 1.2943x; 1.1124x over previous
#include <cuda_runtime.h>
#include <cstdint>

// ---------------------------------------------------------------------------
// AllPassMORRCirculantConv2d  (B=8, Cin=32, H=W=64, K=3, S=1, P=1, Cout=64)
// out[p*8+k] = sum_q (scale[q]*D) * rcp(K2 - 2AR*cos(phase_{p,q,k}))
// phase_{p,q,k} = sum_j inten[q*8+j] * w[p][q][(k-j)&7]   (circular conv n=8)
//
// R15: R11 base + explicit .shared 32-bit addressing with TEMPLATED immediate
//      offsets (fixes R14's "n"-operand compile error) + in-place
//      fma.rn.f32x2. Target: the persistent ~28% alu-pipe overhead.
// ---------------------------------------------------------------------------

#define AA 0.8578
#define RR 0.8985

static constexpr float G2f  = (float)(2.0 * AA * RR);                   // 2AR
static constexpr float K2f  = (float)(1.0 + (AA * RR) * (AA * RR));     // 1+(AR)^2
static constexpr float Df   = (float)((AA * AA + RR * RR) - 1.0
                                      - (AA * RR) * (AA * RR));         // K1-K2
static constexpr float GAINf = 1.6666666666666667f;                     // sqrt(100/36)

#define PH 66
#define PW 66
#define NPAD (8 * 32 * PH * PW)

// smem tile geometry: 16 channels x 3 rows x 65 pair-columns (per phase)
#define TCH   16
#define TROWW 65
#define TSZ   (TCH * 3 * TROWW)      // 3120 float2 = 24960 B

typedef unsigned long long ull;

// Pre-shifted packed image: g_sq2[i] = { s[i], s[i+1] }, s = padded x^2*gain
__device__ float2 g_sq2[NPAD];

// ---------------- packed f32x2 / shared-load helpers -----------------------
__device__ __forceinline__ ull pack2(float lo, float hi) {
    ull r;
    asm("mov.b64 %0, {%1, %2};" : "=l"(r) : "f"(lo), "f"(hi));
    return r;
}
__device__ __forceinline__ void unpack2(ull v, float& lo, float& hi) {
    asm("mov.b64 {%0, %1}, %2;" : "=f"(lo), "=f"(hi) : "l"(v));
}
// in-place packed fma: c = a*b + c
__device__ __forceinline__ void fma2ip(ull& c, ull a, ull b) {
    asm("fma.rn.f32x2 %0, %1, %2, %0;" : "+l"(c) : "l"(a), "l"(b));
}
// ld.shared with template immediate offsets -> guaranteed [r32+imm] form
template <int IMM>
__device__ __forceinline__ ull lds_b64(unsigned base) {
    ull d;
    asm("ld.shared.b64 %0, [%1+%2];" : "=l"(d) : "r"(base), "n"(IMM));
    return d;
}
template <int IMM>
__device__ __forceinline__ void lds_v2b64(unsigned base, ull& d0, ull& d1) {
    asm("ld.shared.v2.b64 {%0, %1}, [%2+%3];"
        : "=l"(d0), "=l"(d1) : "r"(base), "n"(IMM));
}

// tap byte-offset for (ql, t) within an 8-channel group (compile-time)
__host__ __device__ constexpr int toff(int ql, int t) {
    int w = ql * 8 + t;          // 0..71
    int c = w / 9;
    int r = w % 9;
    return (c * 3 + r / 3) * TROWW * 8 + (r % 3) * 8;
}

// ---------------- Kernel 1: pad + square + gain + shift-pack ---------------
__device__ __forceinline__ float pad_val(const float* __restrict__ x, int j) {
    int px = j % PW;
    int t  = j / PW;
    int py = t % PH;
    int bc = t / PH;
    if (px >= 1 && px <= 64 && py >= 1 && py <= 64) {
        float u = x[bc * 4096 + (py - 1) * 64 + (px - 1)];
        return u * u * GAINf;
    }
    return 0.0f;
}

__global__ void prep_kernel(const float* __restrict__ x) {
    int i = blockIdx.x * blockDim.x + threadIdx.x;
    if (i >= NPAD) return;
    float v0 = pad_val(x, i);
    float v1 = (i + 1 < NPAD) ? pad_val(x, i + 1) : 0.0f;
    g_sq2[i] = make_float2(v0, v1);
}

// ---------------- q-body (QL = compile-time) --------------------------------
template <int QL>
__device__ __forceinline__ void do_q(unsigned cbase, unsigned wqb,
                                     float s2, float* acc) {
    ull inten2[8];
    inten2[0] = lds_b64<toff(QL, 0)>(cbase);
    inten2[1] = lds_b64<toff(QL, 1)>(cbase);
    inten2[2] = lds_b64<toff(QL, 2)>(cbase);
    inten2[3] = lds_b64<toff(QL, 3)>(cbase);
    inten2[4] = lds_b64<toff(QL, 4)>(cbase);
    inten2[5] = lds_b64<toff(QL, 5)>(cbase);
    inten2[6] = lds_b64<toff(QL, 6)>(cbase);
    inten2[7] = lds_b64<toff(QL, 7)>(cbase);

    ull w2[8];
    lds_v2b64<QL * 64 + 0>(wqb, w2[0], w2[1]);
    lds_v2b64<QL * 64 + 16>(wqb, w2[2], w2[3]);
    lds_v2b64<QL * 64 + 32>(wqb, w2[4], w2[5]);
    lds_v2b64<QL * 64 + 48>(wqb, w2[6], w2[7]);

    ull ph2[8] = {0ull, 0ull, 0ull, 0ull, 0ull, 0ull, 0ull, 0ull};
#pragma unroll
    for (int j = 0; j < 8; j++) {
#pragma unroll
        for (int k = 0; k < 8; k++)
            fma2ip(ph2[k], inten2[j], w2[(k - j) & 7]);
    }

#pragma unroll
    for (int k = 0; k < 8; k++) {
        float p0, p1;
        unpack2(ph2[k], p0, p1);
        float c0 = __cosf(p0);
        float c1 = __cosf(p1);
        float d0 = fmaf(-G2f, c0, K2f);
        float d1 = fmaf(-G2f, c1, K2f);
        float r0, r1;
        asm("rcp.approx.f32 %0, %1;" : "=f"(r0) : "f"(d0));
        asm("rcp.approx.f32 %0, %1;" : "=f"(r1) : "f"(d1));
        acc[k]     = fmaf(s2, r0, acc[k]);
        acc[8 + k] = fmaf(s2, r1, acc[8 + k]);
    }
}

// ---------------- Kernel 2: main -------------------------------------------
// block = 256 threads = 8 p-warps x 32 pixel-pairs (one row). grid = 512.
// q structure: 2 halves (16 ch each) x 2 groups (9 q = 8 ch) fully unrolled.
__global__ __launch_bounds__(256, 3)
void morr_main_kernel(const float* __restrict__ weight,   // [8][36][8]
                      const float* __restrict__ mscale,   // [19]
                      float* __restrict__ out)            // [8][64][64][64]
{
    __shared__ float2 sp[TSZ];           // staged window pairs: 24960 B
    __shared__ ull    sww[8 * 36 * 8];   // {w,w} duplicated:    18432 B
    __shared__ float  ss2[36];           // scale[q] * D

    const int tid = threadIdx.x;
    const int b   = blockIdx.x >> 6;       // image
    const int y   = blockIdx.x & 63;       // row

    for (int i = tid; i < 2304; i += 256) {
        float wv = weight[i];
        sww[i] = pack2(wv, wv);
    }
    if (tid < 36) {
        float s = (tid < 18) ? mscale[tid] : -mscale[tid - 18];
        ss2[tid] = s * Df;
    }

    const int lane = tid & 31;
    const int p    = tid >> 5;             // warp index = output block p
    const int x    = lane * 2;             // even pixel of the pair

    // 32-bit shared-space base addresses
    const unsigned sp_s  = (unsigned)__cvta_generic_to_shared(sp);
    const unsigned sww_s = (unsigned)__cvta_generic_to_shared(sww);
    const unsigned spx_s = sp_s + (unsigned)(x * 8);
    const unsigned wp_s  = sww_s + (unsigned)(p * 288 * 8);

    const float2* gsrc = g_sq2 + (b * 32) * (PH * PW) + y * PW;

    // acc[k] : pixel x ; acc[8+k] : pixel x+1   (channel p*8+k)
    float acc[16];
#pragma unroll
    for (int i = 0; i < 16; i++) acc[i] = 0.0f;

#pragma unroll 1
    for (int half = 0; half < 2; half++) {
        __syncthreads();                   // prior phase reads done
        const float2* g0 = gsrc + (half * TCH) * (PH * PW);
        for (int i = tid; i < TSZ; i += 256) {
            int c   = i / (3 * TROWW);
            int rem = i - c * (3 * TROWW);
            int rr  = rem / TROWW;
            int pc  = rem - rr * TROWW;
            sp[i] = g0[(c * PH + rr) * PW + pc];
        }
        __syncthreads();

#pragma unroll 1
        for (int grp = 0; grp < 2; grp++) {
            // channels (local) grp*8 .. grp*8+7 ; q = half*18 + grp*9 + ql
            const unsigned cbase = spx_s + (unsigned)(grp * 8 * (3 * TROWW * 8));
            const int      qbase = half * 18 + grp * 9;
            const unsigned wqb   = wp_s + (unsigned)(qbase * 64);
            const float*   sq    = ss2 + qbase;

            do_q<0>(cbase, wqb, sq[0], acc);
            do_q<1>(cbase, wqb, sq[1], acc);
            do_q<2>(cbase, wqb, sq[2], acc);
            do_q<3>(cbase, wqb, sq[3], acc);
            do_q<4>(cbase, wqb, sq[4], acc);
            do_q<5>(cbase, wqb, sq[5], acc);
            do_q<6>(cbase, wqb, sq[6], acc);
            do_q<7>(cbase, wqb, sq[7], acc);
            do_q<8>(cbase, wqb, sq[8], acc);
        }
    }

    float* op = out + (b * 64 + p * 8) * 4096 + y * 64 + x;
#pragma unroll
    for (int k = 0; k < 8; k++)
        *reinterpret_cast<float2*>(op + k * 4096) = make_float2(acc[k], acc[8 + k]);
}

// ---------------- launch ----------------------------------------------------
extern "C" void kernel_launch(void* const* d_in, const int* in_sizes, int n_in,
                              void* d_out, int out_size)
{
    const float* x   = (const float*)d_in[0];   // (8,32,64,64)
    const float* wgt = (const float*)d_in[1];   // (8,36,8)
    const float* ms  = (const float*)d_in[2];   // (19,)
    float* out = (float*)d_out;                 // (8,64,64,64)

    prep_kernel<<<(NPAD + 255) / 256, 256>>>(x);
    morr_main_kernel<<<512, 256>>>(wgt, ms, out);
}

// round 17
// speedup vs baseline: 1.3033x; 1.0069x over previous
#include <cuda_runtime.h>
#include <cstdint>

// ---------------------------------------------------------------------------
// AllPassMORRCirculantConv2d  (B=8, Cin=32, H=W=64, K=3, S=1, P=1, Cout=64)
// out[p*8+k] = sum_q (scale[q]*D) * rcp(K2 - 2AR*cos(phase_{p,q,k}))
// phase_{p,q,k} = sum_j inten[q*8+j] * w[p][q][(k-j)&7]   (circular conv n=8)
//
// R16: j-outer circulant loop (inten loaded per-j, live set ~56 regs) so
//      __launch_bounds__(256,4) fits WITHOUT spilling:
//      4 blocks/SM -> 592 slots >= 512 grid = single wave, 8 warps/SMSP.
// ---------------------------------------------------------------------------

#define AA 0.8578
#define RR 0.8985

static constexpr float G2f  = (float)(2.0 * AA * RR);                   // 2AR
static constexpr float K2f  = (float)(1.0 + (AA * RR) * (AA * RR));     // 1+(AR)^2
static constexpr float Df   = (float)((AA * AA + RR * RR) - 1.0
                                      - (AA * RR) * (AA * RR));         // K1-K2
static constexpr float GAINf = 1.6666666666666667f;                     // sqrt(100/36)

#define PH 66
#define PW 66
#define NPAD (8 * 32 * PH * PW)

// smem tile geometry: 16 channels x 3 rows x 65 pair-columns (per phase)
#define TCH   16
#define TROWW 65
#define TSZ   (TCH * 3 * TROWW)      // 3120 float2 = 24960 B

typedef unsigned long long ull;

// Pre-shifted packed image: g_sq2[i] = { s[i], s[i+1] }, s = padded x^2*gain
__device__ float2 g_sq2[NPAD];

// ---------------- packed f32x2 / shared-load helpers -----------------------
__device__ __forceinline__ ull pack2(float lo, float hi) {
    ull r;
    asm("mov.b64 %0, {%1, %2};" : "=l"(r) : "f"(lo), "f"(hi));
    return r;
}
__device__ __forceinline__ void unpack2(ull v, float& lo, float& hi) {
    asm("mov.b64 {%0, %1}, %2;" : "=f"(lo), "=f"(hi) : "l"(v));
}
// in-place packed fma: c = a*b + c
__device__ __forceinline__ void fma2ip(ull& c, ull a, ull b) {
    asm("fma.rn.f32x2 %0, %1, %2, %0;" : "+l"(c) : "l"(a), "l"(b));
}
template <int IMM>
__device__ __forceinline__ ull lds_b64(unsigned base) {
    ull d;
    asm("ld.shared.b64 %0, [%1+%2];" : "=l"(d) : "r"(base), "n"(IMM));
    return d;
}
template <int IMM>
__device__ __forceinline__ void lds_v2b64(unsigned base, ull& d0, ull& d1) {
    asm("ld.shared.v2.b64 {%0, %1}, [%2+%3];"
        : "=l"(d0), "=l"(d1) : "r"(base), "n"(IMM));
}

// tap byte-offset for (ql, t) within an 8-channel group (compile-time)
__host__ __device__ constexpr int toff(int ql, int t) {
    int w = ql * 8 + t;          // 0..71
    int c = w / 9;
    int r = w % 9;
    return (c * 3 + r / 3) * TROWW * 8 + (r % 3) * 8;
}

// ---------------- Kernel 1: pad + square + gain + shift-pack ---------------
__device__ __forceinline__ float pad_val(const float* __restrict__ x, int j) {
    int px = j % PW;
    int t  = j / PW;
    int py = t % PH;
    int bc = t / PH;
    if (px >= 1 && px <= 64 && py >= 1 && py <= 64) {
        float u = x[bc * 4096 + (py - 1) * 64 + (px - 1)];
        return u * u * GAINf;
    }
    return 0.0f;
}

__global__ void prep_kernel(const float* __restrict__ x) {
    int i = blockIdx.x * blockDim.x + threadIdx.x;
    if (i >= NPAD) return;
    float v0 = pad_val(x, i);
    float v1 = (i + 1 < NPAD) ? pad_val(x, i + 1) : 0.0f;
    g_sq2[i] = make_float2(v0, v1);
}

// ---------------- q-body (QL = compile-time) --------------------------------
// j-outer: inten[j] loaded, consumed by 8 fma2, then dead (live regs ~2).
template <int QL>
__device__ __forceinline__ void do_q(unsigned cbase, unsigned wqb,
                                     float s2, float* acc) {
    ull w2[8];
    lds_v2b64<QL * 64 + 0>(wqb, w2[0], w2[1]);
    lds_v2b64<QL * 64 + 16>(wqb, w2[2], w2[3]);
    lds_v2b64<QL * 64 + 32>(wqb, w2[4], w2[5]);
    lds_v2b64<QL * 64 + 48>(wqb, w2[6], w2[7]);

    ull ph2[8] = {0ull, 0ull, 0ull, 0ull, 0ull, 0ull, 0ull, 0ull};

    {
        ull ij;
        ij = lds_b64<toff(QL, 0)>(cbase);
#pragma unroll
        for (int k = 0; k < 8; k++) fma2ip(ph2[k], ij, w2[(k - 0) & 7]);
        ij = lds_b64<toff(QL, 1)>(cbase);
#pragma unroll
        for (int k = 0; k < 8; k++) fma2ip(ph2[k], ij, w2[(k - 1) & 7]);
        ij = lds_b64<toff(QL, 2)>(cbase);
#pragma unroll
        for (int k = 0; k < 8; k++) fma2ip(ph2[k], ij, w2[(k - 2) & 7]);
        ij = lds_b64<toff(QL, 3)>(cbase);
#pragma unroll
        for (int k = 0; k < 8; k++) fma2ip(ph2[k], ij, w2[(k - 3) & 7]);
        ij = lds_b64<toff(QL, 4)>(cbase);
#pragma unroll
        for (int k = 0; k < 8; k++) fma2ip(ph2[k], ij, w2[(k - 4) & 7]);
        ij = lds_b64<toff(QL, 5)>(cbase);
#pragma unroll
        for (int k = 0; k < 8; k++) fma2ip(ph2[k], ij, w2[(k - 5) & 7]);
        ij = lds_b64<toff(QL, 6)>(cbase);
#pragma unroll
        for (int k = 0; k < 8; k++) fma2ip(ph2[k], ij, w2[(k - 6) & 7]);
        ij = lds_b64<toff(QL, 7)>(cbase);
#pragma unroll
        for (int k = 0; k < 8; k++) fma2ip(ph2[k], ij, w2[(k - 7) & 7]);
    }

#pragma unroll
    for (int k = 0; k < 8; k++) {
        float p0, p1;
        unpack2(ph2[k], p0, p1);
        float c0 = __cosf(p0);
        float c1 = __cosf(p1);
        float d0 = fmaf(-G2f, c0, K2f);
        float d1 = fmaf(-G2f, c1, K2f);
        float r0, r1;
        asm("rcp.approx.f32 %0, %1;" : "=f"(r0) : "f"(d0));
        asm("rcp.approx.f32 %0, %1;" : "=f"(r1) : "f"(d1));
        acc[k]     = fmaf(s2, r0, acc[k]);
        acc[8 + k] = fmaf(s2, r1, acc[8 + k]);
    }
}

// ---------------- Kernel 2: main -------------------------------------------
// block = 256 threads = 8 p-warps x 32 pixel-pairs (one row). grid = 512.
// q structure: 2 halves (16 ch each) x 2 groups (9 q = 8 ch) fully unrolled.
__global__ __launch_bounds__(256, 4)
void morr_main_kernel(const float* __restrict__ weight,   // [8][36][8]
                      const float* __restrict__ mscale,   // [19]
                      float* __restrict__ out)            // [8][64][64][64]
{
    __shared__ float2 sp[TSZ];           // staged window pairs: 24960 B
    __shared__ ull    sww[8 * 36 * 8];   // {w,w} duplicated:    18432 B
    __shared__ float  ss2[36];           // scale[q] * D

    const int tid = threadIdx.x;
    const int b   = blockIdx.x >> 6;       // image
    const int y   = blockIdx.x & 63;       // row

    for (int i = tid; i < 2304; i += 256) {
        float wv = weight[i];
        sww[i] = pack2(wv, wv);
    }
    if (tid < 36) {
        float s = (tid < 18) ? mscale[tid] : -mscale[tid - 18];
        ss2[tid] = s * Df;
    }

    const int lane = tid & 31;
    const int p    = tid >> 5;             // warp index = output block p
    const int x    = lane * 2;             // even pixel of the pair

    const unsigned sp_s  = (unsigned)__cvta_generic_to_shared(sp);
    const unsigned sww_s = (unsigned)__cvta_generic_to_shared(sww);
    const unsigned spx_s = sp_s + (unsigned)(x * 8);
    const unsigned wp_s  = sww_s + (unsigned)(p * 288 * 8);

    const float2* gsrc = g_sq2 + (b * 32) * (PH * PW) + y * PW;

    // acc[k] : pixel x ; acc[8+k] : pixel x+1   (channel p*8+k)
    float acc[16];
#pragma unroll
    for (int i = 0; i < 16; i++) acc[i] = 0.0f;

#pragma unroll 1
    for (int half = 0; half < 2; half++) {
        __syncthreads();                   // prior phase reads done
        const float2* g0 = gsrc + (half * TCH) * (PH * PW);
        for (int i = tid; i < TSZ; i += 256) {
            int c   = i / (3 * TROWW);
            int rem = i - c * (3 * TROWW);
            int rr  = rem / TROWW;
            int pc  = rem - rr * TROWW;
            sp[i] = g0[(c * PH + rr) * PW + pc];
        }
        __syncthreads();

#pragma unroll 1
        for (int grp = 0; grp < 2; grp++) {
            const unsigned cbase = spx_s + (unsigned)(grp * 8 * (3 * TROWW * 8));
            const int      qbase = half * 18 + grp * 9;
            const unsigned wqb   = wp_s + (unsigned)(qbase * 64);
            const float*   sq    = ss2 + qbase;

            do_q<0>(cbase, wqb, sq[0], acc);
            do_q<1>(cbase, wqb, sq[1], acc);
            do_q<2>(cbase, wqb, sq[2], acc);
            do_q<3>(cbase, wqb, sq[3], acc);
            do_q<4>(cbase, wqb, sq[4], acc);
            do_q<5>(cbase, wqb, sq[5], acc);
            do_q<6>(cbase, wqb, sq[6], acc);
            do_q<7>(cbase, wqb, sq[7], acc);
            do_q<8>(cbase, wqb, sq[8], acc);
        }
    }

    float* op = out + (b * 64 + p * 8) * 4096 + y * 64 + x;
#pragma unroll
    for (int k = 0; k < 8; k++)
        *reinterpret_cast<float2*>(op + k * 4096) = make_float2(acc[k], acc[8 + k]);
}

// ---------------- launch ----------------------------------------------------
extern "C" void kernel_launch(void* const* d_in, const int* in_sizes, int n_in,
                              void* d_out, int out_size)
{
    const float* x   = (const float*)d_in[0];   // (8,32,64,64)
    const float* wgt = (const float*)d_in[1];   // (8,36,8)
    const float* ms  = (const float*)d_in[2];   // (19,)
    float* out = (float*)d_out;                 // (8,64,64,64)

    prep_kernel<<<(NPAD + 255) / 256, 256>>>(x);
    morr_main_kernel<<<512, 256>>>(wgt, ms, out);
}